// round 2
// baseline (speedup 1.0000x reference)
#include <cuda_runtime.h>
#include <cuda_bf16.h>
#include <math.h>

// Problem constants
#define B_  64
#define I_  320
#define H_  1536
#define L_  3
#define O_  256
#define H3_ 4608

// GEMM tiling
#define TN 128          // columns (j / output-feature) per block
#define BK 16           // k per smem stage
#define AT_STRIDE 68    // padded smem row stride for A^T tile (64 + 4)
#define WT_STRIDE 132   // padded smem row stride for W^T tile (128 + 4)

#define GH_SPLIT 2
#define GI_SPLIT 4
#define H2O_SPLIT 8

// Device scratch (static, no allocation)
__device__ float g_gh[GH_SPLIT * L_ * B_ * H3_];   // gh partial sums, [l][split][b][j]
__device__ float g_gi_part[GI_SPLIT * B_ * H3_];   // gi partials for current layer (also i2h scratch)
__device__ float g_inp[B_ * H_];                   // i2h output (with bias)
__device__ float g_out_part[H2O_SPLIT * B_ * O_];  // h2o partials

// ---------------------------------------------------------------------------
// C_part[split][b][j] = sum_{k in chunk} A[b][k] * W[j][k]
// A: [64 x K] row-major (lda=K), W: [N x K] row-major.
// grid.x: j tiles (N/128), grid.y: split-K index, grid.z: batch (layer) index.
// ---------------------------------------------------------------------------
__global__ __launch_bounds__(256, 2)
void gemm_nt_kernel(const float* __restrict__ A,
                    const float* __restrict__ W,
                    float* __restrict__ Cpart,
                    int N, int K, int kChunk,
                    long aBatchStride, long wBatchStride, long cBatchStride)
{
    __shared__ float At[BK * AT_STRIDE];
    __shared__ float Wt[BK * WT_STRIDE];

    const int tid = threadIdx.x;
    const int j0  = blockIdx.x * TN;
    const int kBase = blockIdx.y * kChunk;

    A += (long)blockIdx.z * aBatchStride;
    W += (long)blockIdx.z * wBatchStride;
    Cpart += (long)blockIdx.z * cBatchStride + (long)blockIdx.y * B_ * N;

    const int bg = tid >> 5;   // 0..7 -> batch rows bg*8 .. bg*8+7
    const int jg = tid & 31;   // 0..31 -> cols j0 + jg*4 .. +3

    // A-tile loader mapping: 64 rows x 16 k -> 256 threads x 1 float4
    const int bA  = tid >> 2;  // 0..63
    const int kqA = tid & 3;   // 0..3 (float4 group within BK)

    float acc[8][4];
#pragma unroll
    for (int r = 0; r < 8; r++)
#pragma unroll
        for (int c = 0; c < 4; c++) acc[r][c] = 0.0f;

    const int kSteps = kChunk / BK;
    for (int ks = 0; ks < kSteps; ks++) {
        const int kb = kBase + ks * BK;

        // global loads first (helps MLP)
        float4 av = *reinterpret_cast<const float4*>(&A[(long)bA * K + kb + kqA * 4]);
        float4 wv0, wv1;
        {
            int idx = tid;               // rep 0
            int jW = idx >> 2, kqW = idx & 3;
            wv0 = *reinterpret_cast<const float4*>(&W[(long)(j0 + jW) * K + kb + kqW * 4]);
            idx = tid + 256;             // rep 1
            jW = idx >> 2; kqW = idx & 3;
            wv1 = *reinterpret_cast<const float4*>(&W[(long)(j0 + jW) * K + kb + kqW * 4]);
        }

        __syncthreads();  // previous stage fully consumed

        // store A transposed: At[k][b]
        At[(kqA * 4 + 0) * AT_STRIDE + bA] = av.x;
        At[(kqA * 4 + 1) * AT_STRIDE + bA] = av.y;
        At[(kqA * 4 + 2) * AT_STRIDE + bA] = av.z;
        At[(kqA * 4 + 3) * AT_STRIDE + bA] = av.w;

        // store W transposed: Wt[k][j]
        {
            int idx = tid;
            int jW = idx >> 2, kqW = idx & 3;
            Wt[(kqW * 4 + 0) * WT_STRIDE + jW] = wv0.x;
            Wt[(kqW * 4 + 1) * WT_STRIDE + jW] = wv0.y;
            Wt[(kqW * 4 + 2) * WT_STRIDE + jW] = wv0.z;
            Wt[(kqW * 4 + 3) * WT_STRIDE + jW] = wv0.w;
            idx = tid + 256;
            jW = idx >> 2; kqW = idx & 3;
            Wt[(kqW * 4 + 0) * WT_STRIDE + jW] = wv1.x;
            Wt[(kqW * 4 + 1) * WT_STRIDE + jW] = wv1.y;
            Wt[(kqW * 4 + 2) * WT_STRIDE + jW] = wv1.z;
            Wt[(kqW * 4 + 3) * WT_STRIDE + jW] = wv1.w;
        }

        __syncthreads();

#pragma unroll
        for (int k = 0; k < BK; k++) {
            float4 a0 = *reinterpret_cast<const float4*>(&At[k * AT_STRIDE + bg * 8]);
            float4 a1 = *reinterpret_cast<const float4*>(&At[k * AT_STRIDE + bg * 8 + 4]);
            float4 w  = *reinterpret_cast<const float4*>(&Wt[k * WT_STRIDE + jg * 4]);
            float a[8] = {a0.x, a0.y, a0.z, a0.w, a1.x, a1.y, a1.z, a1.w};
            float ww[4] = {w.x, w.y, w.z, w.w};
#pragma unroll
            for (int r = 0; r < 8; r++)
#pragma unroll
                for (int c = 0; c < 4; c++)
                    acc[r][c] = fmaf(a[r], ww[c], acc[r][c]);
        }
    }

    // epilogue: plain store of partial sums
#pragma unroll
    for (int r = 0; r < 8; r++) {
        int b = bg * 8 + r;
        float4 v = make_float4(acc[r][0], acc[r][1], acc[r][2], acc[r][3]);
        *reinterpret_cast<float4*>(&Cpart[(long)b * N + j0 + jg * 4]) = v;
    }
}

// ---------------------------------------------------------------------------
// out[idx] = bias[j] + sum_p parts[p][idx]    (idx over 64*N)
// ---------------------------------------------------------------------------
__global__ void bias_combine_kernel(const float* __restrict__ parts, int nsplit,
                                    const float* __restrict__ bias,
                                    float* __restrict__ out, int N)
{
    int idx = blockIdx.x * 256 + threadIdx.x;
    if (idx >= B_ * N) return;
    int j = idx % N;
    float s = bias[j];
    for (int p = 0; p < nsplit; p++) s += parts[(long)p * B_ * N + idx];
    out[idx] = s;
}

// ---------------------------------------------------------------------------
// GRU gate fusion for one layer:
//   gi = sum of GI_SPLIT partials + b_ih ; gh = sum of GH_SPLIT partials + b_hh
//   r = sigmoid(gi_r + gh_r); z = sigmoid(gi_z + gh_z)
//   n = tanh(gi_n + r * gh_n);  h = (1-z)*n + z*h_prev
// ---------------------------------------------------------------------------
__global__ void gru_gate_kernel(const float* __restrict__ giParts,   // [GI_SPLIT][64][4608]
                                const float* __restrict__ ghParts,   // [GH_SPLIT][64][4608]
                                const float* __restrict__ b_ih,      // [4608]
                                const float* __restrict__ b_hh,      // [4608]
                                const float* __restrict__ h_prev,    // [64][1536]
                                float* __restrict__ h_out)           // [64][1536]
{
    int idx = blockIdx.x * 256 + threadIdx.x;
    if (idx >= B_ * H_) return;
    int b = idx / H_;
    int h = idx % H_;
    long base = (long)b * H3_;

    float gir = b_ih[h], giz = b_ih[H_ + h], gin = b_ih[2 * H_ + h];
#pragma unroll
    for (int p = 0; p < GI_SPLIT; p++) {
        const float* P = giParts + (long)p * B_ * H3_ + base;
        gir += P[h]; giz += P[H_ + h]; gin += P[2 * H_ + h];
    }
    float ghr = b_hh[h], ghz = b_hh[H_ + h], ghn = b_hh[2 * H_ + h];
#pragma unroll
    for (int p = 0; p < GH_SPLIT; p++) {
        const float* P = ghParts + (long)p * B_ * H3_ + base;
        ghr += P[h]; ghz += P[H_ + h]; ghn += P[2 * H_ + h];
    }

    float r = 1.0f / (1.0f + expf(-(gir + ghr)));
    float z = 1.0f / (1.0f + expf(-(giz + ghz)));
    float n = tanhf(gin + r * ghn);
    float hp = h_prev[idx];
    h_out[idx] = (1.0f - z) * n + z * hp;
}

// ---------------------------------------------------------------------------
extern "C" void kernel_launch(void* const* d_in, const int* in_sizes, int n_in,
                              void* d_out, int out_size)
{
    const float* x      = (const float*)d_in[0];   // [64,320]
    const float* hidden = (const float*)d_in[1];   // [3,64,1536]
    const float* w_i2h  = (const float*)d_in[2];   // [1536,320]
    const float* b_i2h  = (const float*)d_in[3];   // [1536]
    const float* w_ih   = (const float*)d_in[4];   // [3,4608,1536]
    const float* w_hh   = (const float*)d_in[5];   // [3,4608,1536]
    const float* b_ih   = (const float*)d_in[6];   // [3,4608]
    const float* b_hh   = (const float*)d_in[7];   // [3,4608]
    const float* w_h2o  = (const float*)d_in[8];   // [256,1536]
    const float* b_h2o  = (const float*)d_in[9];   // [256]
    (void)in_sizes; (void)n_in; (void)out_size;

    float* out     = (float*)d_out;                // [64,256]
    float* hid_out = (float*)d_out + B_ * O_;      // [3,64,1536]

    float *gh_ptr, *gi_ptr, *inp_ptr, *outp_ptr;
    cudaGetSymbolAddress((void**)&gh_ptr,   g_gh);
    cudaGetSymbolAddress((void**)&gi_ptr,   g_gi_part);
    cudaGetSymbolAddress((void**)&inp_ptr,  g_inp);
    cudaGetSymbolAddress((void**)&outp_ptr, g_out_part);

    const long wLayerStride = (long)H3_ * H_;      // 4608*1536
    const long hLayerStride = (long)B_ * H_;       // 64*1536
    const long ghLayerStride = (long)GH_SPLIT * B_ * H3_;

    // 1) gh for all 3 layers, batched, split-K=2: grid (36, 2, 3) = 216 blocks
    gemm_nt_kernel<<<dim3(H3_ / TN, GH_SPLIT, L_), 256>>>(
        hidden, w_hh, gh_ptr, H3_, H_, H_ / GH_SPLIT,
        hLayerStride, wLayerStride, ghLayerStride);

    // 2) i2h: [64,320] @ [320,1536]^T -> g_inp (scratch in g_gi_part)
    gemm_nt_kernel<<<dim3(H_ / TN, 1, 1), 256>>>(
        x, w_i2h, gi_ptr, H_, I_, I_, 0, 0, 0);
    bias_combine_kernel<<<(B_ * H_ + 255) / 256, 256>>>(gi_ptr, 1, b_i2h, inp_ptr, H_);

    // 3) layer chain
    const float* inp = inp_ptr;
    for (int l = 0; l < L_; l++) {
        gemm_nt_kernel<<<dim3(H3_ / TN, GI_SPLIT, 1), 256>>>(
            inp, w_ih + (long)l * wLayerStride, gi_ptr,
            H3_, H_, H_ / GI_SPLIT, 0, 0, 0);
        gru_gate_kernel<<<(B_ * H_ + 255) / 256, 256>>>(
            gi_ptr, gh_ptr + (long)l * ghLayerStride,
            b_ih + (long)l * H3_, b_hh + (long)l * H3_,
            hidden + (long)l * hLayerStride,
            hid_out + (long)l * hLayerStride);
        inp = hid_out + (long)l * hLayerStride;
    }

    // 4) h2o: [64,1536] @ [1536,256]^T -> out
    gemm_nt_kernel<<<dim3(O_ / TN, H2O_SPLIT, 1), 256>>>(
        inp, w_h2o, outp_ptr, O_, H_, H_ / H2O_SPLIT, 0, 0, 0);
    bias_combine_kernel<<<(B_ * O_ + 255) / 256, 256>>>(outp_ptr, H2O_SPLIT, b_h2o, out, O_);
}

// round 4
// speedup vs baseline: 1.5134x; 1.5134x over previous
#include <cuda_runtime.h>
#include <cuda_bf16.h>
#include <math.h>
#include <stdint.h>

// Problem constants
#define B_  64
#define I_  320
#define H_  1536
#define L_  3
#define O_  256
#define H3_ 4608

#define GH_SPLIT 2
#define GI_SPLIT 4
#define I2H_SPLIT 5
#define H2O_SPLIT 24

#define KC 64           // bf16 K elements per smem stage (128B row)
#define TM 128          // weight rows per block (MMA M side)

// Device scratch (static, no allocation)
__device__ float g_gh[GH_SPLIT * L_ * H3_ * B_];    // [l][p][j][b]
__device__ float g_gi_part[GI_SPLIT * H3_ * B_];    // [p][j][b] (also i2h scratch)
__device__ float g_inp[B_ * H_];                    // [b][h]
__device__ float g_out_part[H2O_SPLIT * O_ * B_];   // [p][o][b]

__device__ __forceinline__ uint32_t smem_u32(const void* p) {
    uint32_t a;
    asm("{ .reg .u64 t; cvta.to.shared.u64 t, %1; cvt.u32.u64 %0, t; }" : "=r"(a) : "l"(p));
    return a;
}

// split float pair into bf16-hi pair and bf16-lo (residual) pair, packed 2x16
__device__ __forceinline__ void split2(float a, float b, uint32_t& hi, uint32_t& lo) {
    __nv_bfloat16 ha = __float2bfloat16_rn(a);
    __nv_bfloat16 hb = __float2bfloat16_rn(b);
    float ra = a - __bfloat162float(ha);
    float rb = b - __bfloat162float(hb);
    hi = ((uint32_t)__bfloat16_as_ushort(hb) << 16) | (uint32_t)__bfloat16_as_ushort(ha);
    asm("cvt.rn.bf16x2.f32 %0, %1, %2;" : "=r"(lo) : "f"(rb), "f"(ra));
}

#define LDM_X4(r, addr)                                                        \
    asm volatile("ldmatrix.sync.aligned.m8n8.x4.shared.b16 {%0,%1,%2,%3}, [%4];" \
                 : "=r"((r)[0]), "=r"((r)[1]), "=r"((r)[2]), "=r"((r)[3])      \
                 : "r"(addr))

#define MMA_BF16(c, a, b0, b1)                                                 \
    asm volatile("mma.sync.aligned.m16n8k16.row.col.f32.bf16.bf16.f32 "        \
                 "{%0,%1,%2,%3}, {%4,%5,%6,%7}, {%8,%9}, {%0,%1,%2,%3};"       \
                 : "+f"((c)[0]), "+f"((c)[1]), "+f"((c)[2]), "+f"((c)[3])      \
                 : "r"((a)[0]), "r"((a)[1]), "r"((a)[2]), "r"((a)[3]),         \
                   "r"(b0), "r"(b1))

// ---------------------------------------------------------------------------
// Cpart[p][j][b] = sum_{k in chunk} W[j][k] * Act[b][k]  (3-term bf16 split)
// W: [N x K] row-major, Act: [64 x K] row-major.
// grid.x: j tiles (N/128), grid.y: split-K, grid.z: batched layer.
// Output layout: [z][y][j][b]
// ---------------------------------------------------------------------------
__global__ __launch_bounds__(256)
void gemm_tc_kernel(const float* __restrict__ Act,
                    const float* __restrict__ W,
                    float* __restrict__ Cpart,
                    int N, int K, int kChunk,
                    long aBatchStride, long wBatchStride, long cBatchStride)
{
    __shared__ __align__(128) unsigned char sWhi[TM * 128];
    __shared__ __align__(128) unsigned char sWlo[TM * 128];
    __shared__ __align__(128) unsigned char sAhi[B_ * 128];
    __shared__ __align__(128) unsigned char sAlo[B_ * 128];

    const int tid  = threadIdx.x;
    const int wid  = tid >> 5;
    const int lane = tid & 31;
    const int j0    = blockIdx.x * TM;
    const int kBase = blockIdx.y * kChunk;
    const int nChunks = kChunk / KC;

    Act += (long)blockIdx.z * aBatchStride;
    W   += (long)blockIdx.z * wBatchStride;
    Cpart += (long)blockIdx.z * cBatchStride + (long)blockIdx.y * (long)N * B_;

    // ---- loader mapping ----
    const int wr  = tid >> 1;           // W row 0..127
    const int wk0 = (tid & 1) * 32;     // fp32 k offset within chunk
    const int ar  = tid >> 2;           // Act row 0..63
    const int ak0 = (tid & 3) * 16;
    const int wChunk0 = (tid & 1) * 4;  // 16B chunk base in bf16 row
    const int aChunk0 = (tid & 3) * 2;
    const int wr7 = wr & 7, ar7 = ar & 7;

    // ---- mma mapping: 8 warps = 4(M) x 2(N); warp tile 32x32 ----
    const int wm = wid & 3;
    const int wn = wid >> 2;
    const int r7 = lane & 7;
    const int aRow = lane & 15;         // row within 16 (A frags)
    const int aKhi = lane >> 4;         // k-half for A frag lanes
    const int bNoff = (lane & 7) + ((lane >> 4) << 3);
    const int bKhi = (lane >> 3) & 1;

    const uint32_t sWhiB = smem_u32(sWhi), sWloB = smem_u32(sWlo);
    const uint32_t sAhiB = smem_u32(sAhi), sAloB = smem_u32(sAlo);

    uint32_t aRowOff[2], bRowOff[2];
    aRowOff[0] = (uint32_t)(wm * 32 + aRow) * 128;
    aRowOff[1] = aRowOff[0] + 16 * 128;
    bRowOff[0] = (uint32_t)(wn * 32 + bNoff) * 128;
    bRowOff[1] = bRowOff[0] + 16 * 128;

    float acc[2][4][4];
#pragma unroll
    for (int mt = 0; mt < 2; mt++)
#pragma unroll
        for (int nt = 0; nt < 4; nt++)
#pragma unroll
            for (int q = 0; q < 4; q++) acc[mt][nt][q] = 0.0f;

    // ---- prefetch chunk 0 into registers ----
    float4 wv[8], av[4];
    {
        const float* src = W + (long)(j0 + wr) * K + kBase + wk0;
#pragma unroll
        for (int q = 0; q < 8; q++) wv[q] = *reinterpret_cast<const float4*>(src + q * 4);
        const float* asrc = Act + (long)ar * K + kBase + ak0;
#pragma unroll
        for (int q = 0; q < 4; q++) av[q] = *reinterpret_cast<const float4*>(asrc + q * 4);
    }

    for (int c = 0; c < nChunks; ++c) {
        // ---- convert to bf16 hi/lo ----
        uint32_t whi[16], wlo[16], ahi[8], alo[8];
#pragma unroll
        for (int q = 0; q < 8; q++) {
            split2(wv[q].x, wv[q].y, whi[2 * q], wlo[2 * q]);
            split2(wv[q].z, wv[q].w, whi[2 * q + 1], wlo[2 * q + 1]);
        }
#pragma unroll
        for (int q = 0; q < 4; q++) {
            split2(av[q].x, av[q].y, ahi[2 * q], alo[2 * q]);
            split2(av[q].z, av[q].w, ahi[2 * q + 1], alo[2 * q + 1]);
        }

        if (c) __syncthreads();   // all warps done reading previous stage

        // ---- store tiles with XOR-16B-chunk swizzle (chunk ^= row&7) ----
#pragma unroll
        for (int g = 0; g < 4; g++) {
            uint32_t off = (uint32_t)wr * 128 + (uint32_t)(((wChunk0 + g) ^ wr7) << 4);
            *reinterpret_cast<uint4*>(sWhi + off) =
                make_uint4(whi[4 * g], whi[4 * g + 1], whi[4 * g + 2], whi[4 * g + 3]);
            *reinterpret_cast<uint4*>(sWlo + off) =
                make_uint4(wlo[4 * g], wlo[4 * g + 1], wlo[4 * g + 2], wlo[4 * g + 3]);
        }
#pragma unroll
        for (int g = 0; g < 2; g++) {
            uint32_t off = (uint32_t)ar * 128 + (uint32_t)(((aChunk0 + g) ^ ar7) << 4);
            *reinterpret_cast<uint4*>(sAhi + off) =
                make_uint4(ahi[4 * g], ahi[4 * g + 1], ahi[4 * g + 2], ahi[4 * g + 3]);
            *reinterpret_cast<uint4*>(sAlo + off) =
                make_uint4(alo[4 * g], alo[4 * g + 1], alo[4 * g + 2], alo[4 * g + 3]);
        }
        __syncthreads();

        // ---- prefetch next chunk (hides DRAM behind the MMA loop) ----
        if (c + 1 < nChunks) {
            const int kb = kBase + (c + 1) * KC;
            const float* src = W + (long)(j0 + wr) * K + kb + wk0;
#pragma unroll
            for (int q = 0; q < 8; q++) wv[q] = *reinterpret_cast<const float4*>(src + q * 4);
            const float* asrc = Act + (long)ar * K + kb + ak0;
#pragma unroll
            for (int q = 0; q < 4; q++) av[q] = *reinterpret_cast<const float4*>(asrc + q * 4);
        }

        // ---- MMA mainloop over 4 k16 steps ----
#pragma unroll
        for (int s = 0; s < 4; s++) {
            uint32_t aH[2][4], aL[2][4], bH[2][4], bL[2][4];
            const uint32_t ac = (uint32_t)(((2 * s + aKhi) ^ r7) << 4);
            LDM_X4(aH[0], sWhiB + aRowOff[0] + ac);
            LDM_X4(aH[1], sWhiB + aRowOff[1] + ac);
            LDM_X4(aL[0], sWloB + aRowOff[0] + ac);
            LDM_X4(aL[1], sWloB + aRowOff[1] + ac);
            const uint32_t bc = (uint32_t)(((2 * s + bKhi) ^ r7) << 4);
            LDM_X4(bH[0], sAhiB + bRowOff[0] + bc);
            LDM_X4(bH[1], sAhiB + bRowOff[1] + bc);
            LDM_X4(bL[0], sAloB + bRowOff[0] + bc);
            LDM_X4(bL[1], sAloB + bRowOff[1] + bc);
#pragma unroll
            for (int mt = 0; mt < 2; mt++)
#pragma unroll
                for (int nt = 0; nt < 4; nt++) {
                    const int pr = nt >> 1, hf = (nt & 1) * 2;
                    MMA_BF16(acc[mt][nt], aH[mt], bH[pr][hf], bH[pr][hf + 1]);
                    MMA_BF16(acc[mt][nt], aH[mt], bL[pr][hf], bL[pr][hf + 1]);
                    MMA_BF16(acc[mt][nt], aL[mt], bH[pr][hf], bH[pr][hf + 1]);
                }
        }
    }

    // ---- epilogue: write partial sums, layout [j][b] ----
#pragma unroll
    for (int mt = 0; mt < 2; mt++)
#pragma unroll
        for (int nt = 0; nt < 4; nt++) {
            const int j = j0 + wm * 32 + mt * 16 + (lane >> 2);
            const int b = wn * 32 + nt * 8 + (lane & 3) * 2;
            float2 v0 = make_float2(acc[mt][nt][0], acc[mt][nt][1]);
            float2 v1 = make_float2(acc[mt][nt][2], acc[mt][nt][3]);
            *reinterpret_cast<float2*>(&Cpart[(long)j * B_ + b]) = v0;
            *reinterpret_cast<float2*>(&Cpart[(long)(j + 8) * B_ + b]) = v1;
        }
}

// ---------------------------------------------------------------------------
// out[b][j] = bias[j] + sum_p parts[p][j][b]   (transposing combine)
// ---------------------------------------------------------------------------
__global__ void combine_t_kernel(const float* __restrict__ parts, int nsplit,
                                 const float* __restrict__ bias,
                                 float* __restrict__ out, int N)
{
    int idx = blockIdx.x * 256 + threadIdx.x;
    if (idx >= N * B_) return;
    int j = idx >> 6;
    int b = idx & 63;
    float s = bias[j];
    for (int p = 0; p < nsplit; p++) s += parts[(long)p * N * B_ + idx];
    out[(long)b * N + j] = s;
}

// ---------------------------------------------------------------------------
// GRU gate fusion; gi/gh partials in [p][j(4608)][b] layout.
// ---------------------------------------------------------------------------
__global__ void gru_gate_kernel(const float* __restrict__ giParts,
                                const float* __restrict__ ghParts,
                                const float* __restrict__ b_ih,
                                const float* __restrict__ b_hh,
                                const float* __restrict__ h_prev,   // [b][h]
                                float* __restrict__ h_out)          // [b][h]
{
    int idx = blockIdx.x * 256 + threadIdx.x;
    if (idx >= B_ * H_) return;
    int j = idx >> 6;
    int b = idx & 63;

    float gir = b_ih[j], giz = b_ih[H_ + j], gin = b_ih[2 * H_ + j];
#pragma unroll
    for (int p = 0; p < GI_SPLIT; p++) {
        const float* P = giParts + (long)p * H3_ * B_;
        gir += P[(long)j * B_ + b];
        giz += P[(long)(H_ + j) * B_ + b];
        gin += P[(long)(2 * H_ + j) * B_ + b];
    }
    float ghr = b_hh[j], ghz = b_hh[H_ + j], ghn = b_hh[2 * H_ + j];
#pragma unroll
    for (int p = 0; p < GH_SPLIT; p++) {
        const float* P = ghParts + (long)p * H3_ * B_;
        ghr += P[(long)j * B_ + b];
        ghz += P[(long)(H_ + j) * B_ + b];
        ghn += P[(long)(2 * H_ + j) * B_ + b];
    }

    float r = 1.0f / (1.0f + expf(-(gir + ghr)));
    float z = 1.0f / (1.0f + expf(-(giz + ghz)));
    float n = tanhf(gin + r * ghn);
    float hp = h_prev[(long)b * H_ + j];
    h_out[(long)b * H_ + j] = (1.0f - z) * n + z * hp;
}

// ---------------------------------------------------------------------------
extern "C" void kernel_launch(void* const* d_in, const int* in_sizes, int n_in,
                              void* d_out, int out_size)
{
    const float* x      = (const float*)d_in[0];   // [64,320]
    const float* hidden = (const float*)d_in[1];   // [3,64,1536]
    const float* w_i2h  = (const float*)d_in[2];   // [1536,320]
    const float* b_i2h  = (const float*)d_in[3];   // [1536]
    const float* w_ih   = (const float*)d_in[4];   // [3,4608,1536]
    const float* w_hh   = (const float*)d_in[5];   // [3,4608,1536]
    const float* b_ih   = (const float*)d_in[6];   // [3,4608]
    const float* b_hh   = (const float*)d_in[7];   // [3,4608]
    const float* w_h2o  = (const float*)d_in[8];   // [256,1536]
    const float* b_h2o  = (const float*)d_in[9];   // [256]
    (void)in_sizes; (void)n_in; (void)out_size;

    float* out     = (float*)d_out;                // [64,256]
    float* hid_out = (float*)d_out + B_ * O_;      // [3,64,1536]

    float *gh_ptr, *gi_ptr, *inp_ptr, *outp_ptr;
    cudaGetSymbolAddress((void**)&gh_ptr,   g_gh);
    cudaGetSymbolAddress((void**)&gi_ptr,   g_gi_part);
    cudaGetSymbolAddress((void**)&inp_ptr,  g_inp);
    cudaGetSymbolAddress((void**)&outp_ptr, g_out_part);

    const long wLayerStride = (long)H3_ * H_;
    const long hLayerStride = (long)B_ * H_;
    const long ghLayerStride = (long)GH_SPLIT * H3_ * B_;

    // 1) gh for all 3 layers, batched, split-K=2: grid (36, 2, 3)
    gemm_tc_kernel<<<dim3(H3_ / TM, GH_SPLIT, L_), 256>>>(
        hidden, w_hh, gh_ptr, H3_, H_, H_ / GH_SPLIT,
        hLayerStride, wLayerStride, ghLayerStride);

    // 2) i2h: split-K=5 (one 64-chunk each): grid (12, 5)
    gemm_tc_kernel<<<dim3(H_ / TM, I2H_SPLIT, 1), 256>>>(
        x, w_i2h, gi_ptr, H_, I_, I_ / I2H_SPLIT, 0, 0, 0);
    combine_t_kernel<<<(H_ * B_ + 255) / 256, 256>>>(gi_ptr, I2H_SPLIT, b_i2h, inp_ptr, H_);

    // 3) layer chain
    const float* inp = inp_ptr;
    for (int l = 0; l < L_; l++) {
        gemm_tc_kernel<<<dim3(H3_ / TM, GI_SPLIT, 1), 256>>>(
            inp, w_ih + (long)l * wLayerStride, gi_ptr,
            H3_, H_, H_ / GI_SPLIT, 0, 0, 0);
        gru_gate_kernel<<<(B_ * H_ + 255) / 256, 256>>>(
            gi_ptr, gh_ptr + (long)l * ghLayerStride,
            b_ih + (long)l * H3_, b_hh + (long)l * H3_,
            hidden + (long)l * hLayerStride,
            hid_out + (long)l * hLayerStride);
        inp = hid_out + (long)l * hLayerStride;
    }

    // 4) h2o: grid (2, 24), one 64-chunk each
    gemm_tc_kernel<<<dim3(O_ / TM, H2O_SPLIT, 1), 256>>>(
        inp, w_h2o, outp_ptr, O_, H_, H_ / H2O_SPLIT, 0, 0, 0);
    combine_t_kernel<<<(O_ * B_ + 255) / 256, 256>>>(outp_ptr, H2O_SPLIT, b_h2o, out, O_);
}